// round 4
// baseline (speedup 1.0000x reference)
#include <cuda_runtime.h>
#include <cstdint>

#define NB   160                 // bins per unit length
#define NBX  161                 // x in [0,1], bin = floor(x*NB), clamp 160
#define NBY  240                 // pers in [-0.5,1.0): bin = floor((p+0.5)*NB)
#define NBINS (NBX * NBY)        // 38640
#define HH 50
#define WW 50

__device__ float g_hist[NBINS];
__device__ float g_Gy[NBY * HH];     // [by][h]
__device__ float g_Gx[NBX * WW];     // [bx][w]
__device__ float g_M[HH * NBX];      // [h][bx]
__device__ float g_image[HH * WW];
__device__ float g_rowmax[HH];

__device__ __forceinline__ float fast_exp2(float x) {
    float r; asm("ex2.approx.ftz.f32 %0, %1;" : "=f"(r) : "f"(x)); return r;
}

// ---------- kernel 1: zero hist + build gaussian lookup tables ----------
// work items: [0,NBINS) zero, [NBINS, NBINS+NBY*HH) Gy, then Gx
#define ZW (NBINS + NBY * HH + NBX * WW)
__global__ void k_zero(const float* __restrict__ sigp,
                       const float* __restrict__ gridx,
                       const float* __restrict__ gridy)
{
    int i = blockIdx.x * blockDim.x + threadIdx.x;
    if (i >= ZW) return;
    if (i < NBINS) { g_hist[i] = 0.0f; return; }
    const float sig = *sigp;
    const float c2 = -1.4426950408889634f / (2.0f * sig * sig);
    i -= NBINS;
    if (i < NBY * HH) {
        int by = i / HH, h = i - by * HH;
        float yc = ((float)by + 0.5f) * (1.0f / NB) - 0.5f;   // pers center
        float d = gridy[h] - yc;
        g_Gy[i] = fast_exp2(c2 * d * d);
    } else {
        i -= NBY * HH;
        int bx = i / WW, w = i - bx * WW;
        float xc = ((float)bx + 0.5f) * (1.0f / NB);
        float d = gridx[w] - xc;
        g_Gx[i] = fast_exp2(c2 * d * d);
    }
}

// ---------- kernel 2: nearest-neighbor splat, 1 global red.add per point ----------
__device__ __forceinline__ void splat(float x, float y) {
    float w = y - x;
    float t = fmaf(w, (float)NB, 0.5f * (float)NB);     // (w+0.5)*NB
    if (t >= 0.0f) {
        int by = min((int)t, NBY - 1);
        int bx = min((int)(x * (float)NB), NBX - 1);
        atomicAdd(&g_hist[by * NBX + bx], w);
    }
}
__global__ void __launch_bounds__(512) k_hist(const float2* __restrict__ pairs, int npts)
{
    const int n4 = npts >> 1;
    const float4* p4 = (const float4*)pairs;
    const int stride = gridDim.x * blockDim.x;
    for (int j = blockIdx.x * blockDim.x + threadIdx.x; j < n4; j += stride) {
        float4 q = p4[j];
        splat(q.x, q.y);
        splat(q.z, q.w);
    }
    if ((npts & 1) && blockIdx.x == 0 && threadIdx.x == 0) {
        float2 p = pairs[npts - 1];
        splat(p.x, p.y);
    }
}

// ---------- kernel 3: M[h][bx] = sum_by Gy[by][h] * H[by][bx] ----------
// CTA per bx; thread h. Hist load is uniform (broadcast), table load coalesced.
__global__ void k_gemm_y() {
    const int bx = blockIdx.x;
    const int h = threadIdx.x;          // 64 threads, h<50 active
    if (h >= HH) return;
    float a0 = 0.f, a1 = 0.f, a2 = 0.f, a3 = 0.f;
    #pragma unroll 4
    for (int by = 0; by < NBY; by += 4) {
        a0 = fmaf(g_hist[(by    ) * NBX + bx], g_Gy[(by    ) * HH + h], a0);
        a1 = fmaf(g_hist[(by + 1) * NBX + bx], g_Gy[(by + 1) * HH + h], a1);
        a2 = fmaf(g_hist[(by + 2) * NBX + bx], g_Gy[(by + 2) * HH + h], a2);
        a3 = fmaf(g_hist[(by + 3) * NBX + bx], g_Gy[(by + 3) * HH + h], a3);
    }
    g_M[h * NBX + bx] = (a0 + a1) + (a2 + a3);
}

// ---------- kernel 4: image[h][w] = sum_bx M[h][bx] * Gx[bx][w], + row max ----------
// CTA per h; 256 threads = 4 segs x 64; seg s covers bx = s, s+4, s+8, ...
__global__ void k_gemm_x() {
    __shared__ float sred[4][64];
    __shared__ float wmax[2];
    const int h = blockIdx.x;
    const int tid = threadIdx.x;
    const int seg = tid >> 6;
    const int w = tid & 63;
    float acc = 0.0f;
    if (w < WW) {
        for (int bx = seg; bx < NBX; bx += 4)
            acc = fmaf(g_M[h * NBX + bx], g_Gx[bx * WW + w], acc);
    }
    sred[seg][w] = acc;
    __syncthreads();
    if (seg == 0) {
        float v = ((sred[0][w] + sred[1][w]) + (sred[2][w] + sred[3][w]));
        float m = (w < WW) ? v : -3.0e38f;
        if (w < WW) g_image[h * WW + w] = v;
        #pragma unroll
        for (int off = 16; off > 0; off >>= 1)
            m = fmaxf(m, __shfl_xor_sync(0xFFFFFFFFu, m, off));
        if ((tid & 31) == 0) wmax[tid >> 5] = m;
    }
    __syncthreads();
    if (tid == 0) g_rowmax[h] = fmaxf(wmax[0], wmax[1]);
}

// ---------- kernel 5: global max + normalize ----------
__global__ void k_norm(float* __restrict__ out) {
    __shared__ float s_den;
    const int tid = threadIdx.x;          // 256 threads
    if (tid == 0) {
        float m = -3.0e38f;
        #pragma unroll
        for (int i = 0; i < HH; i++) m = fmaxf(m, g_rowmax[i]);
        s_den = m + 1e-8f;
    }
    __syncthreads();
    const float den = s_den;
    for (int i = tid; i < HH * WW; i += 256) out[i] = g_image[i] / den;
}

extern "C" void kernel_launch(void* const* d_in, const int* in_sizes, int n_in,
                              void* d_out, int out_size) {
    const float2* pairs = (const float2*)d_in[0];
    const float*  sigma = (const float*)d_in[1];
    const float*  gx    = (const float*)d_in[2];
    const float*  gy    = (const float*)d_in[3];
    float* out = (float*)d_out;

    int npts = in_sizes[0] / 2;

    k_zero<<<(ZW + 255) / 256, 256>>>(sigma, gx, gy);
    int n4 = npts >> 1;
    int hgrid = (n4 + 511) / 512;
    if (hgrid > 2048) hgrid = 2048;
    if (hgrid < 1) hgrid = 1;
    k_hist<<<hgrid, 512>>>(pairs, npts);
    k_gemm_y<<<NBX, 64>>>();
    k_gemm_x<<<HH, 256>>>();
    k_norm<<<1, 256>>>(out);
}

// round 5
// speedup vs baseline: 1.3811x; 1.3811x over previous
#include <cuda_runtime.h>
#include <cstdint>

#define NB   160                 // bins per unit length
#define NBX  161                 // x in [0,1]: bin = floor(x*NB), clamp 160
#define NBY  240                 // pers in [-0.5,1.0): bin = floor((p+0.5)*NB)
#define NBINS (NBX * NBY)        // 38640
#define HH 50
#define WW 50

__device__ float g_hist[NBINS];
__device__ float g_image[HH * WW];
__device__ float g_rowmax[HH];

__device__ __forceinline__ float fast_exp2(float x) {
    float r; asm("ex2.approx.ftz.f32 %0, %1;" : "=f"(r) : "f"(x)); return r;
}

// ---------- kernel 1: zero histogram ----------
__global__ void k_zero() {
    int i = blockIdx.x * blockDim.x + threadIdx.x;
    if (i < NBINS) g_hist[i] = 0.0f;
}

// ---------- kernel 2: nearest-neighbor splat, 1 global red.add per point ----------
__device__ __forceinline__ void splat(float x, float y) {
    float w = y - x;
    float t = fmaf(w, (float)NB, 0.5f * (float)NB);     // (w+0.5)*NB
    if (t >= 0.0f) {
        int by = min((int)t, NBY - 1);
        int bx = min((int)(x * (float)NB), NBX - 1);
        atomicAdd(&g_hist[by * NBX + bx], w);
    }
}
__global__ void __launch_bounds__(512) k_hist(const float2* __restrict__ pairs, int npts)
{
    const int n4 = npts >> 1;
    const float4* p4 = (const float4*)pairs;
    const int stride = gridDim.x * blockDim.x;
    for (int j = blockIdx.x * blockDim.x + threadIdx.x; j < n4; j += stride) {
        float4 q = p4[j];
        splat(q.x, q.y);
        splat(q.z, q.w);
    }
    if ((npts & 1) && blockIdx.x == 0 && threadIdx.x == 0) {
        float2 p = pairs[npts - 1];
        splat(p.x, p.y);
    }
}

// ---------- kernel 3: fused tail — one CTA per image row h ----------
// step 1: gyv[by] = exp(c2*(gy[h]-yc)^2)                     (MUFU, 240 lanes)
// step 2: sM[bx]  = sum_by gyv[by] * hist[by][bx]            (coalesced L2 loads)
// step 3: img[h][w] = sum_bx sM[bx] * exp(c2*(gx[w]-xc)^2)   (4-seg reduction)
__global__ void __launch_bounds__(256) k_tail(
    const float* __restrict__ sigp,
    const float* __restrict__ gridx,
    const float* __restrict__ gridy)
{
    __shared__ float gyv[NBY];
    __shared__ float sM[NBX];
    __shared__ float sred[4][64];
    __shared__ float wmax[2];

    const int h = blockIdx.x;
    const int tid = threadIdx.x;
    const float sig = *sigp;
    const float c2 = -1.4426950408889634f / (2.0f * sig * sig);

    if (tid < NBY) {
        float yc = ((float)tid + 0.5f) * (1.0f / NB) - 0.5f;
        float d = gridy[h] - yc;
        gyv[tid] = fast_exp2(c2 * d * d);
    }
    __syncthreads();

    if (tid < NBX) {
        float a0 = 0.f, a1 = 0.f, a2 = 0.f, a3 = 0.f;
        #pragma unroll 4
        for (int by = 0; by < NBY; by += 4) {
            a0 = fmaf(g_hist[(by    ) * NBX + tid], gyv[by    ], a0);
            a1 = fmaf(g_hist[(by + 1) * NBX + tid], gyv[by + 1], a1);
            a2 = fmaf(g_hist[(by + 2) * NBX + tid], gyv[by + 2], a2);
            a3 = fmaf(g_hist[(by + 3) * NBX + tid], gyv[by + 3], a3);
        }
        sM[tid] = (a0 + a1) + (a2 + a3);
    }
    __syncthreads();

    const int seg = tid >> 6;
    const int w = tid & 63;
    float acc = 0.0f;
    if (w < WW) {
        const float gw = gridx[w];
        for (int bx = seg; bx < NBX; bx += 4) {
            float xc = ((float)bx + 0.5f) * (1.0f / NB);
            float d = gw - xc;
            acc = fmaf(sM[bx], fast_exp2(c2 * d * d), acc);
        }
    }
    sred[seg][w] = acc;
    __syncthreads();

    if (seg == 0) {
        float v = (sred[0][w] + sred[1][w]) + (sred[2][w] + sred[3][w]);
        float m = -3.0e38f;
        if (w < WW) { g_image[h * WW + w] = v; m = v; }
        #pragma unroll
        for (int off = 16; off > 0; off >>= 1)
            m = fmaxf(m, __shfl_xor_sync(0xFFFFFFFFu, m, off));
        if ((tid & 31) == 0) wmax[tid >> 5] = m;
    }
    __syncthreads();
    if (tid == 0) g_rowmax[h] = fmaxf(wmax[0], wmax[1]);
}

// ---------- kernel 4: global max (parallel) + normalize ----------
__global__ void __launch_bounds__(256) k_norm(float* __restrict__ out) {
    __shared__ float wred[2];
    __shared__ float s_den;
    const int tid = threadIdx.x;
    float m = (tid < HH) ? g_rowmax[tid] : -3.0e38f;
    if (tid < 64) {
        #pragma unroll
        for (int off = 16; off > 0; off >>= 1)
            m = fmaxf(m, __shfl_xor_sync(0xFFFFFFFFu, m, off));
        if ((tid & 31) == 0) wred[tid >> 5] = m;
    }
    __syncthreads();
    if (tid == 0) s_den = fmaxf(wred[0], wred[1]) + 1e-8f;
    __syncthreads();
    const float den = s_den;
    for (int i = tid; i < HH * WW; i += 256) out[i] = g_image[i] / den;
}

extern "C" void kernel_launch(void* const* d_in, const int* in_sizes, int n_in,
                              void* d_out, int out_size) {
    const float2* pairs = (const float2*)d_in[0];
    const float*  sigma = (const float*)d_in[1];
    const float*  gx    = (const float*)d_in[2];
    const float*  gy    = (const float*)d_in[3];
    float* out = (float*)d_out;

    int npts = in_sizes[0] / 2;

    k_zero<<<(NBINS + 511) / 512, 512>>>();
    int n4 = npts >> 1;
    int hgrid = (n4 + 511) / 512;
    if (hgrid > 2048) hgrid = 2048;
    if (hgrid < 1) hgrid = 1;
    k_hist<<<hgrid, 512>>>(pairs, npts);
    k_tail<<<HH, 256>>>(sigma, gx, gy);
    k_norm<<<1, 256>>>(out);
}